// round 16
// baseline (speedup 1.0000x reference)
#include <cuda_runtime.h>
#include <cuda_fp16.h>

#define HEADS 4
#define C 32
#define F 128
#define NEG_SLOPE 0.02f
#define MAXN 50000
#define MAXE 800000
#define SCAN_TILE 256
#define MAXB ((MAXN + SCAN_TILE - 1) / SCAN_TILE)
#define EPT 4                      // edges per thread in edge kernels

#define FLAG_AGG (1u << 30)
#define FLAG_INC (2u << 30)
#define VAL_MASK 0x3FFFFFFFu

// Scratch (no allocs allowed)
__device__ int          g_srt[MAXE];      // source j per edge, grouped by target i
__device__ int          g_hist[MAXN];     // zeroed by k_scan after consumption
__device__ int          g_off[MAXN + 1];
__device__ int          g_cur[MAXN];
__device__ unsigned int g_status[MAXB];   // lookback status; zeroed by k_hist
__device__ float        g_s0[MAXN * HEADS];
__device__ float        g_s1[MAXN * HEADS];
__device__ __half       g_xh[MAXN * F];   // fp16 mirror of x

__device__ __forceinline__ float lrelu(float a) {
    return a >= 0.f ? a : NEG_SLOPE * a;
}

// Per-block dtype detection over the EPT edges each thread owns.
// int64 indices < 2^32 => odd 32-bit words all 0; int32 random => ~never.
__device__ __forceinline__ int detect_is64_multi(const void* ei, int base, int E) {
    unsigned int v = 0u;
#pragma unroll
    for (int r = 0; r < EPT; r++) {
        int e = base + r * SCAN_TILE;
        if (e < E) v |= ((const unsigned int*)ei)[2 * e + 1];
    }
    return __syncthreads_or((int)v) ? 0 : 1;
}

// Kernel 1: histogram of targets, 4 edges/thread; also zeroes scan status.
__global__ void k_hist(const void* __restrict__ ei, int E, int NB) {
    int base = blockIdx.x * (SCAN_TILE * EPT) + threadIdx.x;
    int t = blockIdx.x * blockDim.x + threadIdx.x;
    if (t < NB) g_status[t] = 0u;
    int is64 = detect_is64_multi(ei, base, E);
#pragma unroll
    for (int r = 0; r < EPT; r++) {
        int e = base + r * SCAN_TILE;
        if (e < E) {
            int i = is64 ? (int)((const long long*)ei)[e] : ((const int*)ei)[e];
            atomicAdd(&g_hist[i], 1);
        }
    }
}

// Kernel 2: scores + fp16 mirror (forked stream, overlaps hist->scan->scatter)
__global__ void k_scores(const float* __restrict__ x, const float* __restrict__ W, int N) {
    int t = blockIdx.x * blockDim.x + threadIdx.x;
    int n = t >> 5;
    int q = t & 31;
    if (n >= N) return;
    float4 v = *(const float4*)(x + (size_t)n * F + q * 4);

    __half2 h0 = __floats2half2_rn(v.x, v.y);
    __half2 h1 = __floats2half2_rn(v.z, v.w);
    *(__half2*)(g_xh + (size_t)n * F + q * 4) = h0;
    *(__half2*)(g_xh + (size_t)n * F + q * 4 + 2) = h1;

    int c = q & 7;
    float4 w0 = ((const float4*)W)[c];
    float4 w1 = ((const float4*)(W + C))[c];
    float p0 = v.x * w0.x + v.y * w0.y + v.z * w0.z + v.w * w0.w;
    float p1 = v.x * w1.x + v.y * w1.y + v.z * w1.z + v.w * w1.w;
#pragma unroll
    for (int o = 4; o; o >>= 1) {
        p0 += __shfl_down_sync(0xFFFFFFFFu, p0, o, 8);
        p1 += __shfl_down_sync(0xFFFFFFFFu, p1, o, 8);
    }
    if (c == 0) {
        int h = q >> 3;
        g_s0[n * 4 + h] = p0;
        g_s1[n * 4 + h] = p1;
    }
}

// Kernel 3: single-pass decoupled-lookback exclusive scan of g_hist -> g_off.
__global__ void k_scan(int N, int NB) {
    __shared__ int warp_sums[8];
    __shared__ int s_total;
    __shared__ int s_base;
    int tid = threadIdx.x;
    int lane = tid & 31;
    int wid = tid >> 5;
    int idx = blockIdx.x * SCAN_TILE + tid;
    int v = (idx < N) ? g_hist[idx] : 0;

    int p = v;
#pragma unroll
    for (int o = 1; o < 32; o <<= 1) {
        int u = __shfl_up_sync(0xFFFFFFFFu, p, o);
        if (lane >= o) p += u;
    }
    if (lane == 31) warp_sums[wid] = p;
    __syncthreads();
    if (wid == 0) {
        int s = (lane < 8) ? warp_sums[lane] : 0;
#pragma unroll
        for (int o = 1; o < 8; o <<= 1) {
            int u = __shfl_up_sync(0xFFFFFFFFu, s, o);
            if (lane >= o) s += u;
        }
        if (lane < 8) warp_sums[lane] = s;
    }
    __syncthreads();
    int incl = p + (wid ? warp_sums[wid - 1] : 0);

    if (tid == SCAN_TILE - 1) {
        s_total = incl;
        if (blockIdx.x == 0) {
            s_base = 0;
            atomicExch(&g_status[0], FLAG_INC | (unsigned)incl);
        } else {
            atomicExch(&g_status[blockIdx.x], FLAG_AGG | (unsigned)incl);
        }
    }
    __syncthreads();

    if (wid == 0 && blockIdx.x > 0) {
        int sum = 0;
        int end = blockIdx.x;
        while (true) {
            int b = end - 1 - lane;
            unsigned s = 0;
            if (b >= 0) {
                do { s = atomicAdd(&g_status[b], 0u); } while (s == 0u);
            }
            unsigned incMask = __ballot_sync(0xFFFFFFFFu, (b < 0) || (s & FLAG_INC));
            int firstInc = __ffs(incMask) - 1;
            int contrib = 0;
            if (firstInc < 0 || lane < firstInc)
                contrib = (int)(s & VAL_MASK);
            else if (lane == firstInc && b >= 0)
                contrib = (int)(s & VAL_MASK);
#pragma unroll
            for (int o = 16; o; o >>= 1)
                contrib += __shfl_xor_sync(0xFFFFFFFFu, contrib, o);
            sum += contrib;
            if (incMask) break;
            end -= 32;
        }
        if (lane == 0) {
            s_base = sum;
            atomicExch(&g_status[blockIdx.x], FLAG_INC | (unsigned)(sum + s_total));
        }
    }
    __syncthreads();

    int base = s_base;
    if (idx < N) {
        int o = base + incl - v;
        g_off[idx] = o;
        g_cur[idx] = o;
        g_hist[idx] = 0;
    }
    if (blockIdx.x == NB - 1 && tid == SCAN_TILE - 1)
        g_off[N] = base + s_total;
}

// Kernel 4: scatter into CSR order, 4 edges/thread => 4 independent
// atomic->store chains in flight per thread (attacks ~320cyc ATOMG latency).
__global__ void k_scatter(const void* __restrict__ ei, int E) {
    int base = blockIdx.x * (SCAN_TILE * EPT) + threadIdx.x;
    int is64 = detect_is64_multi(ei, base, E);
    int iv[EPT], jv[EPT];
#pragma unroll
    for (int r = 0; r < EPT; r++) {
        int e = base + r * SCAN_TILE;
        if (e < E) {
            if (is64) {
                const long long* p = (const long long*)ei;
                iv[r] = (int)p[e];
                jv[r] = (int)p[(size_t)E + e];
            } else {
                const int* p = (const int*)ei;
                iv[r] = p[e];
                jv[r] = p[E + e];
            }
        } else {
            iv[r] = -1;
        }
    }
    int pos[EPT];
#pragma unroll
    for (int r = 0; r < EPT; r++)
        if (iv[r] >= 0) pos[r] = atomicAdd(&g_cur[iv[r]], 1);
#pragma unroll
    for (int r = 0; r < EPT; r++)
        if (iv[r] >= 0) g_srt[pos[r]] = jv[r];
}

// Kernel 5: aggregation, warp per node, lane owns 4 channels (8B fp16 gather).
__global__ void k_agg(float* __restrict__ out, int N) {
    int t = blockIdx.x * blockDim.x + threadIdx.x;
    int n = t >> 5;
    int lane = t & 31;
    if (n >= N) return;
    int start = g_off[n];
    int cnt = g_off[n + 1] - start;
    int q = lane;
    int h = q >> 3;
    float s0h = g_s0[n * 4 + h];
    float d = 0.f;
    float4 acc = make_float4(0.f, 0.f, 0.f, 0.f);

    for (int e0 = 0; e0 < cnt; e0 += 32) {
        int batch = min(32, cnt - e0);
        int jv = (lane < batch) ? g_srt[start + e0 + lane] : 0;
#pragma unroll 8
        for (int k = 0; k < batch; k++) {
            int j = __shfl_sync(0xFFFFFFFFu, jv, k);
            float a = lrelu(s0h + g_s1[j * 4 + h]);
            float wgt = __expf(a);
            d += wgt;
            uint2 raw = *(const uint2*)(g_xh + (size_t)j * F + q * 4);
            float2 v01 = __half22float2(*(__half2*)&raw.x);
            float2 v23 = __half22float2(*(__half2*)&raw.y);
            acc.x += v01.x * wgt;
            acc.y += v01.y * wgt;
            acc.z += v23.x * wgt;
            acc.w += v23.y * wgt;
        }
    }
    float rdh = __fdividef(1.0f, d + 1e-16f);
    acc.x *= rdh; acc.y *= rdh; acc.z *= rdh; acc.w *= rdh;
    *(float4*)(out + (size_t)n * F + q * 4) = acc;
}

extern "C" void kernel_launch(void* const* d_in, const int* in_sizes, int n_in,
                              void* d_out, int out_size) {
    const float* x = nullptr;
    const void* ei = nullptr;
    const float* W = nullptr;
    int N = 50000, E = 800000;
    for (int k = 0; k < n_in; k++) {
        int s = in_sizes[k];
        if (s == 64) {
            W = (const float*)d_in[k];
        } else if (s < 4000000) {
            ei = d_in[k];
            E = s / 2;
        } else {
            x = (const float*)d_in[k];
            N = s / F;
        }
    }
    float* out = (float*)d_out;

    static cudaStream_t s_side = nullptr;
    static cudaEvent_t ev_fork = nullptr, ev_join = nullptr;
    if (!s_side) {
        cudaStreamCreateWithFlags(&s_side, cudaStreamNonBlocking);
        cudaEventCreateWithFlags(&ev_fork, cudaEventDisableTiming);
        cudaEventCreateWithFlags(&ev_join, cudaEventDisableTiming);
    }

    const int TB = 256;
    int NB = (N + SCAN_TILE - 1) / SCAN_TILE;
    int EB = (E + TB * EPT - 1) / (TB * EPT);
    long long st = (long long)N * 32;

    // Fork: scores on side stream, overlapped with hist->scan->scatter.
    cudaEventRecord(ev_fork, 0);
    cudaStreamWaitEvent(s_side, ev_fork, 0);
    k_scores<<<(int)((st + TB - 1) / TB), TB, 0, s_side>>>(x, W, N);
    cudaEventRecord(ev_join, s_side);

    k_hist<<<EB, TB>>>(ei, E, NB);
    k_scan<<<NB, SCAN_TILE>>>(N, NB);
    k_scatter<<<EB, TB>>>(ei, E);

    cudaStreamWaitEvent(0, ev_join, 0);
    k_agg<<<(int)((st + TB - 1) / TB), TB>>>(out, N);
}

// round 17
// speedup vs baseline: 1.0561x; 1.0561x over previous
#include <cuda_runtime.h>
#include <cuda_fp16.h>

#define HEADS 4
#define C 32
#define F 128
#define NEG_SLOPE 0.02f
#define MAXN 50000
#define MAXE 800000
#define SCAN_TILE 256
#define MAXB ((MAXN + SCAN_TILE - 1) / SCAN_TILE)

#define FLAG_AGG (1u << 30)
#define FLAG_INC (2u << 30)
#define VAL_MASK 0x3FFFFFFFu

// Scratch (no allocs allowed)
__device__ int          g_srt[MAXE];      // source j per edge, grouped by target i
__device__ int          g_rank[MAXE];     // edge's rank within its target segment
__device__ int          g_hist[MAXN];     // zeroed by k_scan after consumption
__device__ int          g_off[MAXN + 1];
__device__ unsigned int g_status[MAXB];   // lookback status; zeroed by k_hist
__device__ float        g_s0[MAXN * HEADS];
__device__ float        g_s1[MAXN * HEADS];
__device__ __half       g_xh[MAXN * F];   // fp16 mirror of x

__device__ __forceinline__ float lrelu(float a) {
    return a >= 0.f ? a : NEG_SLOPE * a;
}

// Per-block dtype detection: int64 indices < 2^32 => odd 32-bit words all 0.
__device__ __forceinline__ int detect_is64(const void* ei, int e, int E) {
    unsigned int v = (e < E) ? ((const unsigned int*)ei)[2 * e + 1] : 0u;
    return __syncthreads_or((int)v) ? 0 : 1;
}

// Kernel 1: histogram of targets; the atomic's RETURN VALUE is the edge's
// rank within its segment (stored for the atomic-free scatter).
// Also zeroes scan status words for this run.
__global__ void k_hist(const void* __restrict__ ei, int E, int NB) {
    int e = blockIdx.x * blockDim.x + threadIdx.x;
    if (e < NB) g_status[e] = 0u;
    int is64 = detect_is64(ei, e, E);
    if (e >= E) return;
    int i = is64 ? (int)((const long long*)ei)[e] : ((const int*)ei)[e];
    g_rank[e] = atomicAdd(&g_hist[i], 1);
}

// Kernel 2: scores + fp16 mirror (forked stream, overlaps hist->scan->scatter)
__global__ void k_scores(const float* __restrict__ x, const float* __restrict__ W, int N) {
    int t = blockIdx.x * blockDim.x + threadIdx.x;
    int n = t >> 5;
    int q = t & 31;
    if (n >= N) return;
    float4 v = *(const float4*)(x + (size_t)n * F + q * 4);

    __half2 h0 = __floats2half2_rn(v.x, v.y);
    __half2 h1 = __floats2half2_rn(v.z, v.w);
    *(__half2*)(g_xh + (size_t)n * F + q * 4) = h0;
    *(__half2*)(g_xh + (size_t)n * F + q * 4 + 2) = h1;

    int c = q & 7;
    float4 w0 = ((const float4*)W)[c];
    float4 w1 = ((const float4*)(W + C))[c];
    float p0 = v.x * w0.x + v.y * w0.y + v.z * w0.z + v.w * w0.w;
    float p1 = v.x * w1.x + v.y * w1.y + v.z * w1.z + v.w * w1.w;
#pragma unroll
    for (int o = 4; o; o >>= 1) {
        p0 += __shfl_down_sync(0xFFFFFFFFu, p0, o, 8);
        p1 += __shfl_down_sync(0xFFFFFFFFu, p1, o, 8);
    }
    if (c == 0) {
        int h = q >> 3;
        g_s0[n * 4 + h] = p0;
        g_s1[n * 4 + h] = p1;
    }
}

// Kernel 3: single-pass decoupled-lookback exclusive scan of g_hist -> g_off.
// Also zeroes g_hist and writes g_off[N].
__global__ void k_scan(int N, int NB) {
    __shared__ int warp_sums[8];
    __shared__ int s_total;
    __shared__ int s_base;
    int tid = threadIdx.x;
    int lane = tid & 31;
    int wid = tid >> 5;
    int idx = blockIdx.x * SCAN_TILE + tid;
    int v = (idx < N) ? g_hist[idx] : 0;

    int p = v;
#pragma unroll
    for (int o = 1; o < 32; o <<= 1) {
        int u = __shfl_up_sync(0xFFFFFFFFu, p, o);
        if (lane >= o) p += u;
    }
    if (lane == 31) warp_sums[wid] = p;
    __syncthreads();
    if (wid == 0) {
        int s = (lane < 8) ? warp_sums[lane] : 0;
#pragma unroll
        for (int o = 1; o < 8; o <<= 1) {
            int u = __shfl_up_sync(0xFFFFFFFFu, s, o);
            if (lane >= o) s += u;
        }
        if (lane < 8) warp_sums[lane] = s;
    }
    __syncthreads();
    int incl = p + (wid ? warp_sums[wid - 1] : 0);

    if (tid == SCAN_TILE - 1) {
        s_total = incl;
        if (blockIdx.x == 0) {
            s_base = 0;
            atomicExch(&g_status[0], FLAG_INC | (unsigned)incl);
        } else {
            atomicExch(&g_status[blockIdx.x], FLAG_AGG | (unsigned)incl);
        }
    }
    __syncthreads();

    if (wid == 0 && blockIdx.x > 0) {
        int sum = 0;
        int end = blockIdx.x;
        while (true) {
            int b = end - 1 - lane;
            unsigned s = 0;
            if (b >= 0) {
                do { s = atomicAdd(&g_status[b], 0u); } while (s == 0u);
            }
            unsigned incMask = __ballot_sync(0xFFFFFFFFu, (b < 0) || (s & FLAG_INC));
            int firstInc = __ffs(incMask) - 1;
            int contrib = 0;
            if (firstInc < 0 || lane < firstInc)
                contrib = (int)(s & VAL_MASK);
            else if (lane == firstInc && b >= 0)
                contrib = (int)(s & VAL_MASK);
#pragma unroll
            for (int o = 16; o; o >>= 1)
                contrib += __shfl_xor_sync(0xFFFFFFFFu, contrib, o);
            sum += contrib;
            if (incMask) break;
            end -= 32;
        }
        if (lane == 0) {
            s_base = sum;
            atomicExch(&g_status[blockIdx.x], FLAG_INC | (unsigned)(sum + s_total));
        }
    }
    __syncthreads();

    int base = s_base;
    if (idx < N) {
        g_off[idx] = base + incl - v;
        g_hist[idx] = 0;
    }
    if (blockIdx.x == NB - 1 && tid == SCAN_TILE - 1)
        g_off[N] = base + s_total;
}

// Kernel 4: ATOMIC-FREE scatter: pos = off[i] + rank[e]. Coalesced edge+rank
// reads, L2-resident off gather, scattered 4B store.
__global__ void k_scatter(const void* __restrict__ ei, int E) {
    int e = blockIdx.x * blockDim.x + threadIdx.x;
    int is64 = detect_is64(ei, e, E);
    if (e >= E) return;
    int i, j;
    if (is64) {
        const long long* p = (const long long*)ei;
        i = (int)p[e];
        j = (int)p[(size_t)E + e];
    } else {
        const int* p = (const int*)ei;
        i = p[e];
        j = p[E + e];
    }
    g_srt[g_off[i] + g_rank[e]] = j;
}

// Kernel 5: aggregation, warp per node, lane owns 4 channels (8B fp16 gather).
__global__ void k_agg(float* __restrict__ out, int N) {
    int t = blockIdx.x * blockDim.x + threadIdx.x;
    int n = t >> 5;
    int lane = t & 31;
    if (n >= N) return;
    int start = g_off[n];
    int cnt = g_off[n + 1] - start;
    int q = lane;
    int h = q >> 3;
    float s0h = g_s0[n * 4 + h];
    float d = 0.f;
    float4 acc = make_float4(0.f, 0.f, 0.f, 0.f);

    for (int e0 = 0; e0 < cnt; e0 += 32) {
        int batch = min(32, cnt - e0);
        int jv = (lane < batch) ? g_srt[start + e0 + lane] : 0;
#pragma unroll 8
        for (int k = 0; k < batch; k++) {
            int j = __shfl_sync(0xFFFFFFFFu, jv, k);
            float a = lrelu(s0h + g_s1[j * 4 + h]);
            float wgt = __expf(a);
            d += wgt;
            uint2 raw = *(const uint2*)(g_xh + (size_t)j * F + q * 4);
            float2 v01 = __half22float2(*(__half2*)&raw.x);
            float2 v23 = __half22float2(*(__half2*)&raw.y);
            acc.x += v01.x * wgt;
            acc.y += v01.y * wgt;
            acc.z += v23.x * wgt;
            acc.w += v23.y * wgt;
        }
    }
    float rdh = __fdividef(1.0f, d + 1e-16f);
    acc.x *= rdh; acc.y *= rdh; acc.z *= rdh; acc.w *= rdh;
    *(float4*)(out + (size_t)n * F + q * 4) = acc;
}

extern "C" void kernel_launch(void* const* d_in, const int* in_sizes, int n_in,
                              void* d_out, int out_size) {
    const float* x = nullptr;
    const void* ei = nullptr;
    const float* W = nullptr;
    int N = 50000, E = 800000;
    for (int k = 0; k < n_in; k++) {
        int s = in_sizes[k];
        if (s == 64) {
            W = (const float*)d_in[k];
        } else if (s < 4000000) {
            ei = d_in[k];
            E = s / 2;
        } else {
            x = (const float*)d_in[k];
            N = s / F;
        }
    }
    float* out = (float*)d_out;

    static cudaStream_t s_side = nullptr;
    static cudaEvent_t ev_fork = nullptr, ev_join = nullptr;
    if (!s_side) {
        cudaStreamCreateWithFlags(&s_side, cudaStreamNonBlocking);
        cudaEventCreateWithFlags(&ev_fork, cudaEventDisableTiming);
        cudaEventCreateWithFlags(&ev_join, cudaEventDisableTiming);
    }

    const int TB = 256;
    int NB = (N + SCAN_TILE - 1) / SCAN_TILE;
    long long st = (long long)N * 32;

    // Fork: scores on side stream, overlapped with hist->scan->scatter.
    cudaEventRecord(ev_fork, 0);
    cudaStreamWaitEvent(s_side, ev_fork, 0);
    k_scores<<<(int)((st + TB - 1) / TB), TB, 0, s_side>>>(x, W, N);
    cudaEventRecord(ev_join, s_side);

    k_hist<<<(E + TB - 1) / TB, TB>>>(ei, E, NB);
    k_scan<<<NB, SCAN_TILE>>>(N, NB);
    k_scatter<<<(E + TB - 1) / TB, TB>>>(ei, E);

    cudaStreamWaitEvent(0, ev_join, 0);
    k_agg<<<(int)((st + TB - 1) / TB), TB>>>(out, N);
}